// round 6
// baseline (speedup 1.0000x reference)
#include <cuda_runtime.h>
#include <cuda_fp16.h>
#include <cstdint>

#define DEV __device__ __forceinline__

// problem dims
#define N_IMG 256
#define D_INF 768
#define D_HID 768
#define D_OUTF 512
#define M_GAL 100000
#define TOPK 5

// scratch (no cudaMalloc allowed)
__device__ __half g_Ahi1[N_IMG*D_INF];
__device__ __half g_Alo1[N_IMG*D_INF];
__device__ __half g_Ahi2[N_IMG*D_HID];
__device__ __half g_Alo2[N_IMG*D_HID];
__device__ float  g_IMG [N_IMG*D_OUTF];
__device__ __half g_AN  [N_IMG*D_OUTF];
// topk scratch
__device__ float g_pmax[100];
__device__ float g_psum[100];
__device__ int   g_pidx[100*TOPK];
__device__ float g_pval[100*TOPK];

DEV void cp16(void* s, const void* g){
  uint32_t sa = (uint32_t)__cvta_generic_to_shared(s);
  asm volatile("cp.async.cg.shared.global [%0], [%1], 16;" :: "r"(sa), "l"(g));
}
DEV void cp_commit(){ asm volatile("cp.async.commit_group;"); }
DEV void cp_wait0(){ asm volatile("cp.async.wait_group 0;"); }
DEV void cp_wait1(){ asm volatile("cp.async.wait_group 1;"); }

DEV void ldsm4(uint32_t* d, const void* p){
  uint32_t a=(uint32_t)__cvta_generic_to_shared(p);
  asm volatile("ldmatrix.sync.aligned.m8n8.x4.shared.b16 {%0,%1,%2,%3}, [%4];"
    : "=r"(d[0]),"=r"(d[1]),"=r"(d[2]),"=r"(d[3]) : "r"(a));
}
DEV void mma_fp16(float* c, const uint32_t* a, const uint32_t* b){
  asm volatile("mma.sync.aligned.m16n8k16.row.col.f32.f16.f16.f32 "
    "{%0,%1,%2,%3}, {%4,%5,%6,%7}, {%8,%9}, {%0,%1,%2,%3};"
    : "+f"(c[0]),"+f"(c[1]),"+f"(c[2]),"+f"(c[3])
    : "r"(a[0]),"r"(a[1]),"r"(a[2]),"r"(a[3]),"r"(b[0]),"r"(b[1]));
}

// =========== MLP GEMM: 3-term fp16, BM=64 BN=64 BK=64, 3-stage pipeline ===========
template<bool RELU, bool SPLIT>
__global__ __launch_bounds__(256, 1)
void hgemm3(const __half* __restrict__ Ahi, const __half* __restrict__ Alo,
            const float* __restrict__ B, const float* __restrict__ bias,
            float* __restrict__ Cf, __half* __restrict__ Chi, __half* __restrict__ Clo,
            int Ntot, int K){
  constexpr int SABB = 144;
  constexpr int ABYTES = 64*SABB;              // 9216
  constexpr int OB     = 2*ABYTES;
  constexpr int BBYTES = 64*SABB;
  constexpr int STAGE  = OB + 2*BBYTES;        // 36864

  extern __shared__ __align__(16) char sm[];
  const int tid = threadIdx.x, lane = tid & 31, warp = tid >> 5;
  const int wm = (warp & 1) * 32, wn = (warp >> 1) * 16;
  const int m0 = blockIdx.x * 64, n0 = blockIdx.y * 64;
  const int nch = K / 64;

  float acc[2][2][4];
#pragma unroll
  for (int a=0;a<2;a++)
#pragma unroll
    for (int b=0;b<2;b++)
#pragma unroll
      for (int c=0;c<4;c++) acc[a][b][c]=0.f;

  float4 breg[2][2];
  auto loadB = [&](int kb){
#pragma unroll
    for (int s=0;s<2;s++){
      int seg = tid + s*256;
      int row = seg >> 3, sc = seg & 7;
      const float4* p = reinterpret_cast<const float4*>(B + (size_t)(n0+row)*K + kb + sc*8);
      breg[s][0] = p[0]; breg[s][1] = p[1];
    }
  };
  auto stsB = [&](int slot){
#pragma unroll
    for (int s=0;s<2;s++){
      int seg = tid + s*256;
      int row = seg >> 3, sc = seg & 7;
      float f[8] = {breg[s][0].x,breg[s][0].y,breg[s][0].z,breg[s][0].w,
                    breg[s][1].x,breg[s][1].y,breg[s][1].z,breg[s][1].w};
      union { uint4 u; __half h[8]; } ph, pl;
#pragma unroll
      for (int e=0;e<8;e++){
        __half hh = __float2half_rn(f[e]);
        ph.h[e] = hh;
        pl.h[e] = __float2half_rn(f[e] - __half2float(hh));
      }
      char* dst = sm + slot*STAGE + OB + row*SABB + sc*16;
      *reinterpret_cast<uint4*>(dst)          = ph.u;
      *reinterpret_cast<uint4*>(dst + BBYTES) = pl.u;
    }
  };
  auto cpA = [&](int slot, int kb){
#pragma unroll
    for (int s=0;s<2;s++){
      int seg = tid + s*256;
      int row = seg >> 3, sc = seg & 7;
      size_t go = (size_t)(m0 + row)*K + kb + sc*8;
      char* d = sm + slot*STAGE + row*SABB + sc*16;
      cp16(d,          Ahi + go);
      cp16(d + ABYTES, Alo + go);
    }
  };
  auto do_mma = [&](int slot){
    char* sa  = sm + slot*STAGE;
    char* sbh = sa + OB;
    const int ar = lane & 15, ac = (lane >> 4) * 8;
    const int q = lane >> 3, rq = lane & 7;
    const int bro = ((q>>1)*8 + rq)*SABB + (q&1)*16;
#pragma unroll
    for (int ks=0; ks<4; ks++){
      const int kk = ks*16;
      uint32_t ah[2][4], al[2][4], bh[4], bl[4];
#pragma unroll
      for (int ms=0; ms<2; ms++){
        char* pa = sa + (wm + ms*16 + ar)*SABB + (kk + ac)*2;
        ldsm4(ah[ms], pa);
        ldsm4(al[ms], pa + ABYTES);
      }
      {
        char* pb = sbh + wn*SABB + kk*2 + bro;
        ldsm4(bh, pb);
        ldsm4(bl, pb + BBYTES);
      }
#pragma unroll
      for (int ms=0; ms<2; ms++)
#pragma unroll
        for (int ns=0; ns<2; ns++){
          mma_fp16(acc[ms][ns], ah[ms], bh + ns*2);
          mma_fp16(acc[ms][ns], al[ms], bh + ns*2);
          mma_fp16(acc[ms][ns], ah[ms], bl + ns*2);
        }
    }
  };

  // 3-stage pipeline. Slot math mod 3; cpA for chunk i+2 issued AFTER sync(i)
  // so laggards finishing mma(i-1) (same slot) are provably done.
  loadB(0);
  cpA(0, 0); cp_commit();
  cpA(1, 64); cp_commit();
  for (int i=0; i<nch; i++){
    const int slot = i % 3;
    stsB(slot);                           // chunk i (regs from prev iter / prologue)
    if (i+1 < nch) loadB((i+1)*64);
    if (i < nch-1) cp_wait1(); else cp_wait0();   // drain A group i
    __syncthreads();
    if (i+2 < nch){ cpA((i+2)%3, (i+2)*64); cp_commit(); }
    do_mma(slot);
  }

  const int gr = lane >> 2, gc = (lane & 3) * 2;
#pragma unroll
  for (int ms=0; ms<2; ms++)
#pragma unroll
    for (int ns=0; ns<2; ns++){
      int row = m0 + wm + ms*16 + gr;
      int col = n0 + wn + ns*8 + gc;
      float v0=acc[ms][ns][0], v1=acc[ms][ns][1], v2=acc[ms][ns][2], v3=acc[ms][ns][3];
      float c0=bias[col], c1=bias[col+1];
      v0+=c0; v1+=c1; v2+=c0; v3+=c1;
      if (RELU){ v0=fmaxf(v0,0.f); v1=fmaxf(v1,0.f); v2=fmaxf(v2,0.f); v3=fmaxf(v3,0.f); }
      if (SPLIT){
        __half h0=__float2half_rn(v0), h1=__float2half_rn(v1);
        __half h2=__float2half_rn(v2), h3=__float2half_rn(v3);
        *reinterpret_cast<__half2*>(&Chi[(size_t)row*Ntot + col])     = __halves2half2(h0,h1);
        *reinterpret_cast<__half2*>(&Chi[(size_t)(row+8)*Ntot + col]) = __halves2half2(h2,h3);
        *reinterpret_cast<__half2*>(&Clo[(size_t)row*Ntot + col]) =
            __halves2half2(__float2half_rn(v0-__half2float(h0)), __float2half_rn(v1-__half2float(h1)));
        *reinterpret_cast<__half2*>(&Clo[(size_t)(row+8)*Ntot + col]) =
            __halves2half2(__float2half_rn(v2-__half2float(h2)), __float2half_rn(v3-__half2float(h3)));
      } else {
        *reinterpret_cast<float2*>(&Cf[(size_t)row*Ntot + col])     = make_float2(v0,v1);
        *reinterpret_cast<float2*>(&Cf[(size_t)(row+8)*Ntot + col]) = make_float2(v2,v3);
      }
    }
}

// =========== big GEMM, FUSED f32->fp16 B: BM=128 BN=64 BK=32, 3-stage, 2 CTA/SM ===========
__global__ __launch_bounds__(256, 2)
void hgemm1F(const __half* __restrict__ A, const float* __restrict__ B,
             float* __restrict__ C, int Ntot, int K){
  constexpr int SRS    = 80;                   // f16 row stride bytes (32 halfs + pad)
  constexpr int ABYTES = 128*SRS;              // 10240
  constexpr int BBYTES = 64*SRS;               // 5120
  constexpr int STAGE  = ABYTES + BBYTES;      // 15360; x3 = 46080
  constexpr int BK     = 32;

  extern __shared__ __align__(16) char sm[];
  const int tid = threadIdx.x, lane = tid & 31, warp = tid >> 5;
  const int wm = (warp & 3) * 32, wn = (warp >> 2) * 32;   // 4x2 warps, 32x32 tiles
  const int m0 = blockIdx.x * 128, n0 = blockIdx.y * 64;
  const int nch = K / BK;                      // 16

  float acc[2][4][4];
#pragma unroll
  for (int a=0;a<2;a++)
#pragma unroll
    for (int b=0;b<4;b++)
#pragma unroll
      for (int c=0;c<4;c++) acc[a][b][c]=0.f;

  float4 breg[2];
  auto loadB = [&](int kb){
#pragma unroll
    for (int s=0;s<2;s++){
      int seg = tid + s*256;                   // 512 segs: 64 rows x 8 float4s
      int row = seg >> 3, sc = seg & 7;
      int gn = n0 + row; if (gn > Ntot-1) gn = Ntot-1;
      breg[s] = *reinterpret_cast<const float4*>(B + (size_t)gn*K + kb + sc*4);
    }
  };
  auto stsB = [&](int slot){
#pragma unroll
    for (int s=0;s<2;s++){
      int seg = tid + s*256;
      int row = seg >> 3, sc = seg & 7;
      union { uint2 u; __half2 h[2]; } o;
      o.h[0] = __floats2half2_rn(breg[s].x, breg[s].y);
      o.h[1] = __floats2half2_rn(breg[s].z, breg[s].w);
      *reinterpret_cast<uint2*>(sm + slot*STAGE + ABYTES + row*SRS + sc*8) = o.u;
    }
  };
  auto cpA = [&](int slot, int kb){
#pragma unroll
    for (int s=0;s<2;s++){
      int seg = tid + s*256;                   // 512 segs: 128 rows x 4 x 16B
      int row = seg >> 2, sc = seg & 3;
      cp16(sm + slot*STAGE + row*SRS + sc*16,
           A + (size_t)(m0 + row)*K + kb + sc*8);
    }
  };
  auto do_mma = [&](int slot){
    char* sa = sm + slot*STAGE;
    char* sb = sa + ABYTES;
    const int ar = lane & 15, ac = (lane >> 4) * 8;
    const int q = lane >> 3, rq = lane & 7;
    const int bro = ((q>>1)*8 + rq)*SRS + (q&1)*16;
#pragma unroll
    for (int ks=0; ks<2; ks++){
      const int kk = ks*16;
      uint32_t af[2][4], bf[8];
#pragma unroll
      for (int ms=0; ms<2; ms++)
        ldsm4(af[ms], sa + (wm + ms*16 + ar)*SRS + (kk + ac)*2);
#pragma unroll
      for (int nsp=0; nsp<2; nsp++)
        ldsm4(bf + nsp*4, sb + (wn + nsp*16)*SRS + kk*2 + bro);
#pragma unroll
      for (int ms=0; ms<2; ms++)
#pragma unroll
        for (int ns=0; ns<4; ns++)
          mma_fp16(acc[ms][ns], af[ms], bf + ns*2);
    }
  };

  loadB(0);
  cpA(0, 0);  cp_commit();
  cpA(1, BK); cp_commit();
  for (int i=0; i<nch; i++){
    const int slot = i % 3;
    stsB(slot);
    if (i+1 < nch) loadB((i+1)*BK);
    if (i < nch-1) cp_wait1(); else cp_wait0();
    __syncthreads();
    if (i+2 < nch){ cpA((i+2)%3, (i+2)*BK); cp_commit(); }
    do_mma(slot);
  }

  const int gr = lane >> 2, gc = (lane & 3) * 2;
#pragma unroll
  for (int ms=0; ms<2; ms++)
#pragma unroll
    for (int ns=0; ns<4; ns++){
      int row = m0 + wm + ms*16 + gr;
      int col = n0 + wn + ns*8 + gc;
      if (col < Ntot){
        *reinterpret_cast<float2*>(&C[(size_t)row*Ntot + col])     = make_float2(acc[ms][ns][0], acc[ms][ns][1]);
        *reinterpret_cast<float2*>(&C[(size_t)(row+8)*Ntot + col]) = make_float2(acc[ms][ns][2], acc[ms][ns][3]);
      }
    }
}

// ---------------- small kernels ----------------
__global__ void split_k(const float* __restrict__ src, __half* __restrict__ hi,
                        __half* __restrict__ lo, int n){
  int i = blockIdx.x*256 + threadIdx.x;
  if (i < n){
    float x = src[i];
    __half h = __float2half_rn(x);
    hi[i] = h;
    lo[i] = __float2half_rn(x - __half2float(h));
  }
}

__global__ void rownorm_h(const float* __restrict__ img, const float* __restrict__ ls,
                          __half* __restrict__ outh){
  __shared__ float red[128];
  __shared__ float sc_s;
  int row = blockIdx.x, t = threadIdx.x;
  float v[4]; float s = 0.f;
#pragma unroll
  for (int j=0;j<4;j++){ v[j] = img[row*D_OUTF + t + j*128]; s += v[j]*v[j]; }
  red[t] = s; __syncthreads();
  for (int off=64; off>0; off>>=1){ if (t<off) red[t]+=red[t+off]; __syncthreads(); }
  if (t==0) sc_s = expf(*ls) / sqrtf(red[0]);
  __syncthreads();
  float sc = sc_s;
#pragma unroll
  for (int j=0;j<4;j++)
    outh[row*D_OUTF + t + j*128] = __float2half_rn(v[j]*sc);
}

// topk phase 1: 100 blocks x 256 threads over row 0 (1000 logits each)
__global__ void topk_p1(const float* __restrict__ logits){
  __shared__ float rv[256];
  __shared__ int   ri[256];
  __shared__ int   sel[TOPK];
  __shared__ float bmax_s;
  int t = threadIdx.x, b = blockIdx.x;
  int lo = b*1000, hi = lo + 1000;

  float m = -3.4e38f;
  for (int i = lo + t; i < hi; i += 256) m = fmaxf(m, logits[i]);
  rv[t] = m; __syncthreads();
  for (int s=128; s>0; s>>=1){ if (t<s) rv[t]=fmaxf(rv[t],rv[t+s]); __syncthreads(); }
  if (t==0) bmax_s = rv[0];
  __syncthreads();
  float bm = bmax_s;

  float sum = 0.f;
  for (int i = lo + t; i < hi; i += 256) sum += expf(logits[i] - bm);
  rv[t] = sum; __syncthreads();
  for (int s=128; s>0; s>>=1){ if (t<s) rv[t]+=rv[t+s]; __syncthreads(); }
  if (t==0){ g_pmax[b] = bm; g_psum[b] = rv[0]; }
  __syncthreads();

  for (int r = 0; r < TOPK; r++){
    float bv = -3.4e38f; int bi = 0x7fffffff;
    for (int i = lo + t; i < hi; i += 256){
      bool skip = false;
#pragma unroll
      for (int j = 0; j < TOPK; j++) if (j < r && sel[j] == i) skip = true;
      float v = logits[i];
      if (!skip && (v > bv || (v == bv && i < bi))){ bv = v; bi = i; }
    }
    rv[t] = bv; ri[t] = bi; __syncthreads();
    for (int s=128; s>0; s>>=1){
      if (t<s){
        if (rv[t+s] > rv[t] || (rv[t+s] == rv[t] && ri[t+s] < ri[t])){
          rv[t]=rv[t+s]; ri[t]=ri[t+s];
        }
      }
      __syncthreads();
    }
    if (t==0){ sel[r] = ri[0]; g_pidx[b*TOPK + r] = ri[0]; g_pval[b*TOPK + r] = rv[0]; }
    __syncthreads();
  }
}

// topk phase 2: merge 100 partials, write gps + probs tail
__global__ void topk_p2(const float* __restrict__ gps, float* __restrict__ out_tail){
  __shared__ float rv[512];
  __shared__ int   ri[512];
  __shared__ float gM_s, gS_s;
  int t = threadIdx.x;

  float m = (t < 100) ? g_pmax[t] : -3.4e38f;
  rv[t] = m; __syncthreads();
  for (int s=256; s>0; s>>=1){ if (t<s) rv[t]=fmaxf(rv[t],rv[t+s]); __syncthreads(); }
  if (t==0) gM_s = rv[0];
  __syncthreads();
  float M = gM_s;

  float sum = (t < 100) ? g_psum[t] * expf(g_pmax[t] - M) : 0.f;
  rv[t] = sum; __syncthreads();
  for (int s=256; s>0; s>>=1){ if (t<s) rv[t]+=rv[t+s]; __syncthreads(); }
  if (t==0) gS_s = rv[0];
  __syncthreads();
  float S = gS_s;

  float cv = (t < 100*TOPK) ? g_pval[t] : -3.4e38f;
  int   ci = (t < 100*TOPK) ? g_pidx[t] : 0x7fffffff;

  for (int r = 0; r < TOPK; r++){
    rv[t] = cv; ri[t] = ci; __syncthreads();
    for (int s=256; s>0; s>>=1){
      if (t<s){
        if (rv[t+s] > rv[t] || (rv[t+s] == rv[t] && ri[t+s] < ri[t])){
          rv[t]=rv[t+s]; ri[t]=ri[t+s];
        }
      }
      __syncthreads();
    }
    if (t == 0){
      int gi = ri[0];
      out_tail[2*r]   = gps[2*gi];
      out_tail[2*r+1] = gps[2*gi+1];
      out_tail[2*TOPK + r] = expf(rv[0] - M) / S;
    }
    __syncthreads();
    if (ci == ri[0]) cv = -3.4e38f;
    __syncthreads();
  }
}

extern "C" void kernel_launch(void* const* d_in, const int* in_sizes, int n_in,
                              void* d_out, int out_size){
  const float* img_feats   = (const float*)d_in[0];
  const float* w1          = (const float*)d_in[1];
  const float* b1          = (const float*)d_in[2];
  const float* w2          = (const float*)d_in[3];
  const float* b2          = (const float*)d_in[4];
  const float* logit_scale = (const float*)d_in[5];
  const float* loc_feats   = (const float*)d_in[6];
  const float* gps         = (const float*)d_in[7];
  float* out = (float*)d_out;

  void *ahi1,*alo1,*ahi2,*alo2,*imgb,*an;
  cudaGetSymbolAddress(&ahi1, g_Ahi1);
  cudaGetSymbolAddress(&alo1, g_Alo1);
  cudaGetSymbolAddress(&ahi2, g_Ahi2);
  cudaGetSymbolAddress(&alo2, g_Alo2);
  cudaGetSymbolAddress(&imgb, g_IMG);
  cudaGetSymbolAddress(&an,   g_AN);

  cudaFuncSetAttribute(hgemm3<true,true>,   cudaFuncAttributeMaxDynamicSharedMemorySize, 110592);
  cudaFuncSetAttribute(hgemm3<false,false>, cudaFuncAttributeMaxDynamicSharedMemorySize, 110592);
  cudaFuncSetAttribute(hgemm1F,             cudaFuncAttributeMaxDynamicSharedMemorySize, 46080);

  // 1) split input to fp16 hi/lo
  split_k<<<(N_IMG*D_INF+255)/256,256>>>(img_feats, (__half*)ahi1, (__half*)alo1, N_IMG*D_INF);
  // 2) H = relu(X W1^T + b1), epilogue writes fp16 hi/lo split directly
  hgemm3<true,true><<<dim3(4, D_HID/64), 256, 110592>>>(
      (__half*)ahi1, (__half*)alo1, w1, b1, nullptr, (__half*)ahi2, (__half*)alo2, D_HID, D_INF);
  // 3) IMG = H W2^T + b2 (f32 out)
  hgemm3<false,false><<<dim3(4, D_OUTF/64), 256, 110592>>>(
      (__half*)ahi2, (__half*)alo2, w2, b2, (float*)imgb, nullptr, nullptr, D_OUTF, D_HID);
  // 4) normalize rows, fold in exp(logit_scale) -> single fp16
  rownorm_h<<<N_IMG,128>>>((const float*)imgb, logit_scale, (__half*)an);
  // 5) logits = (s*img_n) @ loc_feats^T, f32->fp16 conversion fused
  hgemm1F<<<dim3(2, (M_GAL+63)/64), 256, 46080>>>(
      (__half*)an, loc_feats, out, M_GAL, D_OUTF);
  // 6) row-0 softmax + top-5
  topk_p1<<<100,256>>>(out);
  topk_p2<<<1,512>>>(gps, out + (size_t)N_IMG*M_GAL);
}

// round 8
// speedup vs baseline: 1.5101x; 1.5101x over previous
#include <cuda_runtime.h>
#include <cuda_fp16.h>
#include <cstdint>

#define DEV __device__ __forceinline__

// problem dims
#define N_IMG 256
#define D_INF 768
#define D_HID 768
#define D_OUTF 512
#define M_GAL 100000
#define TOPK 5

// scratch (no cudaMalloc allowed)
__device__ __half g_Ahi1[N_IMG*D_INF];
__device__ __half g_Alo1[N_IMG*D_INF];
__device__ __half g_Ahi2[N_IMG*D_HID];
__device__ __half g_Alo2[N_IMG*D_HID];
__device__ float  g_IMG [N_IMG*D_OUTF];
__device__ __half g_AN  [N_IMG*D_OUTF];
// topk scratch
__device__ float g_pmax[100];
__device__ float g_psum[100];
__device__ int   g_pidx[100*TOPK];
__device__ float g_pval[100*TOPK];

DEV void cp16(void* s, const void* g){
  uint32_t sa = (uint32_t)__cvta_generic_to_shared(s);
  asm volatile("cp.async.cg.shared.global [%0], [%1], 16;" :: "r"(sa), "l"(g));
}
DEV void cp_commit(){ asm volatile("cp.async.commit_group;"); }
DEV void cp_wait0(){ asm volatile("cp.async.wait_group 0;"); }
DEV void cp_wait1(){ asm volatile("cp.async.wait_group 1;"); }

DEV void ldsm4(uint32_t* d, const void* p){
  uint32_t a=(uint32_t)__cvta_generic_to_shared(p);
  asm volatile("ldmatrix.sync.aligned.m8n8.x4.shared.b16 {%0,%1,%2,%3}, [%4];"
    : "=r"(d[0]),"=r"(d[1]),"=r"(d[2]),"=r"(d[3]) : "r"(a));
}
DEV void mma_fp16(float* c, const uint32_t* a, const uint32_t* b){
  asm volatile("mma.sync.aligned.m16n8k16.row.col.f32.f16.f16.f32 "
    "{%0,%1,%2,%3}, {%4,%5,%6,%7}, {%8,%9}, {%0,%1,%2,%3};"
    : "+f"(c[0]),"+f"(c[1]),"+f"(c[2]),"+f"(c[3])
    : "r"(a[0]),"r"(a[1]),"r"(a[2]),"r"(a[3]),"r"(b[0]),"r"(b[1]));
}

// =========== MLP GEMM (round-5 exact): 3-term fp16, BM=64 BN=64 BK=64, 2-stage ===========
template<bool RELU, bool SPLIT>
__global__ __launch_bounds__(256, 2)
void hgemm3(const __half* __restrict__ Ahi, const __half* __restrict__ Alo,
            const float* __restrict__ B, const float* __restrict__ bias,
            float* __restrict__ Cf, __half* __restrict__ Chi, __half* __restrict__ Clo,
            int Ntot, int K){
  constexpr int SABB = 144;
  constexpr int ABYTES = 64*SABB;
  constexpr int OB     = 2*ABYTES;
  constexpr int BBYTES = 64*SABB;
  constexpr int STAGE  = OB + 2*BBYTES;        // 36864

  extern __shared__ __align__(16) char sm[];
  const int tid = threadIdx.x, lane = tid & 31, warp = tid >> 5;
  const int wm = (warp & 1) * 32, wn = (warp >> 1) * 16;
  const int m0 = blockIdx.x * 64, n0 = blockIdx.y * 64;
  const int nch = K / 64;

  float acc[2][2][4];
#pragma unroll
  for (int a=0;a<2;a++)
#pragma unroll
    for (int b=0;b<2;b++)
#pragma unroll
      for (int c=0;c<4;c++) acc[a][b][c]=0.f;

  float4 breg[2][2];
  auto loadB = [&](int kb){
#pragma unroll
    for (int s=0;s<2;s++){
      int seg = tid + s*256;
      int row = seg >> 3, sc = seg & 7;
      const float4* p = reinterpret_cast<const float4*>(B + (size_t)(n0+row)*K + kb + sc*8);
      breg[s][0] = p[0]; breg[s][1] = p[1];
    }
  };
  auto stsB = [&](int buf){
#pragma unroll
    for (int s=0;s<2;s++){
      int seg = tid + s*256;
      int row = seg >> 3, sc = seg & 7;
      float f[8] = {breg[s][0].x,breg[s][0].y,breg[s][0].z,breg[s][0].w,
                    breg[s][1].x,breg[s][1].y,breg[s][1].z,breg[s][1].w};
      union { uint4 u; __half h[8]; } ph, pl;
#pragma unroll
      for (int e=0;e<8;e++){
        __half hh = __float2half_rn(f[e]);
        ph.h[e] = hh;
        pl.h[e] = __float2half_rn(f[e] - __half2float(hh));
      }
      char* dst = sm + buf*STAGE + OB + row*SABB + sc*16;
      *reinterpret_cast<uint4*>(dst)          = ph.u;
      *reinterpret_cast<uint4*>(dst + BBYTES) = pl.u;
    }
  };
  auto cpA = [&](int buf, int kb){
#pragma unroll
    for (int s=0;s<2;s++){
      int seg = tid + s*256;
      int row = seg >> 3, sc = seg & 7;
      size_t go = (size_t)(m0 + row)*K + kb + sc*8;
      char* d = sm + buf*STAGE + row*SABB + sc*16;
      cp16(d,          Ahi + go);
      cp16(d + ABYTES, Alo + go);
    }
  };
  auto do_mma = [&](int buf){
    char* sa  = sm + buf*STAGE;
    char* sbh = sa + OB;
    const int ar = lane & 15, ac = (lane >> 4) * 8;
    const int q = lane >> 3, rq = lane & 7;
    const int bro = ((q>>1)*8 + rq)*SABB + (q&1)*16;
#pragma unroll
    for (int ks=0; ks<4; ks++){
      const int kk = ks*16;
      uint32_t ah[2][4], al[2][4], bh[4], bl[4];
#pragma unroll
      for (int ms=0; ms<2; ms++){
        char* pa = sa + (wm + ms*16 + ar)*SABB + (kk + ac)*2;
        ldsm4(ah[ms], pa);
        ldsm4(al[ms], pa + ABYTES);
      }
      {
        char* pb = sbh + wn*SABB + kk*2 + bro;
        ldsm4(bh, pb);
        ldsm4(bl, pb + BBYTES);
      }
#pragma unroll
      for (int ms=0; ms<2; ms++)
#pragma unroll
        for (int ns=0; ns<2; ns++){
          mma_fp16(acc[ms][ns], ah[ms], bh + ns*2);
          mma_fp16(acc[ms][ns], al[ms], bh + ns*2);
          mma_fp16(acc[ms][ns], ah[ms], bl + ns*2);
        }
    }
  };

  loadB(0); stsB(0); cpA(0,0); cp_commit();
  for (int i=0; i<nch; i++){
    const int buf = i & 1;
    if (i+1 < nch) loadB((i+1)*64);
    cp_wait0();
    __syncthreads();
    if (i+1 < nch){ cpA(buf^1, (i+1)*64); cp_commit(); }
    do_mma(buf);
    if (i+1 < nch) stsB(buf^1);
  }

  const int gr = lane >> 2, gc = (lane & 3) * 2;
#pragma unroll
  for (int ms=0; ms<2; ms++)
#pragma unroll
    for (int ns=0; ns<2; ns++){
      int row = m0 + wm + ms*16 + gr;
      int col = n0 + wn + ns*8 + gc;
      float v0=acc[ms][ns][0], v1=acc[ms][ns][1], v2=acc[ms][ns][2], v3=acc[ms][ns][3];
      float c0=bias[col], c1=bias[col+1];
      v0+=c0; v1+=c1; v2+=c0; v3+=c1;
      if (RELU){ v0=fmaxf(v0,0.f); v1=fmaxf(v1,0.f); v2=fmaxf(v2,0.f); v3=fmaxf(v3,0.f); }
      if (SPLIT){
        __half h0=__float2half_rn(v0), h1=__float2half_rn(v1);
        __half h2=__float2half_rn(v2), h3=__float2half_rn(v3);
        *reinterpret_cast<__half2*>(&Chi[(size_t)row*Ntot + col])     = __halves2half2(h0,h1);
        *reinterpret_cast<__half2*>(&Chi[(size_t)(row+8)*Ntot + col]) = __halves2half2(h2,h3);
        *reinterpret_cast<__half2*>(&Clo[(size_t)row*Ntot + col]) =
            __halves2half2(__float2half_rn(v0-__half2float(h0)), __float2half_rn(v1-__half2float(h1)));
        *reinterpret_cast<__half2*>(&Clo[(size_t)(row+8)*Ntot + col]) =
            __halves2half2(__float2half_rn(v2-__half2float(h2)), __float2half_rn(v3-__half2float(h3)));
      } else {
        *reinterpret_cast<float2*>(&Cf[(size_t)row*Ntot + col])     = make_float2(v0,v1);
        *reinterpret_cast<float2*>(&Cf[(size_t)(row+8)*Ntot + col]) = make_float2(v2,v3);
      }
    }
}

// ===== big GEMM, fused conv, B f32 staged via cp.async: BM=128 BN=128 BK=32, 3-slot =====
__global__ __launch_bounds__(256, 2)
void hgemmBig(const __half* __restrict__ A, const float* __restrict__ B,
              float* __restrict__ C, int Ntot, int K){
  constexpr int SRS   = 80;                    // fp16 row stride (32 halfs + pad)
  constexpr int ABYTES= 128*SRS;               // 10240
  constexpr int BF32B = 128*128;               // 16384 (32 f32 = 128B rows, unpadded)
  constexpr int OB32  = ABYTES;
  constexpr int OB16  = ABYTES + BF32B;
  constexpr int STAGE = ABYTES + BF32B + 128*SRS;  // 36864 ; x3 = 110592
  constexpr int BK    = 32;

  extern __shared__ __align__(16) char sm[];
  const int tid = threadIdx.x, lane = tid & 31, warp = tid >> 5;
  const int wm = (warp & 1) * 64, wn = (warp >> 1) * 32;   // 2x4 warps, 64x32 tiles
  const int m0 = blockIdx.x * 128, n0 = blockIdx.y * 128;
  const int nch = K / BK;                      // 16

  float acc[4][4][4];
#pragma unroll
  for (int a=0;a<4;a++)
#pragma unroll
    for (int b=0;b<4;b++)
#pragma unroll
      for (int c=0;c<4;c++) acc[a][b][c]=0.f;

  auto issue = [&](int slot, int kb){
    char* sb = sm + slot*STAGE;
    // A fp16: 128 rows x 4 x 16B = 512 segs (2/thread)
#pragma unroll
    for (int s=0;s<2;s++){
      int seg = tid + s*256;
      int row = seg >> 2, sc = seg & 3;
      cp16(sb + row*SRS + sc*16, A + (size_t)(m0 + row)*K + kb + sc*8);
    }
    // B f32: 128 rows x 8 x 16B = 1024 segs (4/thread)
#pragma unroll
    for (int s=0;s<4;s++){
      int seg = tid + s*256;
      int row = seg >> 3, sc = seg & 7;
      int gn = n0 + row; if (gn > Ntot-1) gn = Ntot-1;
      cp16(sb + OB32 + row*128 + sc*16, B + (size_t)gn*K + kb + sc*4);
    }
    cp_commit();
  };
  auto conv = [&](int slot){
    char* sb = sm + slot*STAGE;
    // 512 units: each = 8 f32 (32B) -> 8 f16 (16B). row=unit>>2, sc=unit&3.
#pragma unroll
    for (int s=0;s<2;s++){
      int unit = tid + s*256;
      int row = unit >> 2, sc = unit & 3;
      const float4* src = reinterpret_cast<const float4*>(sb + OB32 + row*128 + sc*32);
      float4 a = src[0], b = src[1];
      union { uint4 u; __half2 h[4]; } o;
      o.h[0] = __floats2half2_rn(a.x, a.y);
      o.h[1] = __floats2half2_rn(a.z, a.w);
      o.h[2] = __floats2half2_rn(b.x, b.y);
      o.h[3] = __floats2half2_rn(b.z, b.w);
      *reinterpret_cast<uint4*>(sb + OB16 + row*SRS + sc*16) = o.u;
    }
  };
  auto do_mma = [&](int slot){
    char* sa = sm + slot*STAGE;
    char* sb = sa + OB16;
    const int ar = lane & 15, ac = (lane >> 4) * 8;
    const int q = lane >> 3, rq = lane & 7;
    const int bro = ((q>>1)*8 + rq)*SRS + (q&1)*16;
#pragma unroll
    for (int ks=0; ks<2; ks++){
      const int kk = ks*16;
      uint32_t af[4][4], bf[8];
#pragma unroll
      for (int ms=0; ms<4; ms++)
        ldsm4(af[ms], sa + (wm + ms*16 + ar)*SRS + (kk + ac)*2);
#pragma unroll
      for (int nsp=0; nsp<2; nsp++)
        ldsm4(bf + nsp*4, sb + (wn + nsp*16)*SRS + kk*2 + bro);
#pragma unroll
      for (int ms=0; ms<4; ms++)
#pragma unroll
        for (int ns=0; ns<4; ns++)
          mma_fp16(acc[ms][ns], af[ms], bf + ns*2);
    }
  };

  issue(0, 0);
  issue(1, BK);
  for (int i=0; i<nch; i++){
    const int slot = i % 3;
    // group i must be complete; groups 0..i+1 committed so far
    if (i < nch-1) cp_wait1(); else cp_wait0();
    __syncthreads();                       // also: all warps done with mma(i-1)
    if (i+2 < nch) issue((i+2)%3, (i+2)*BK);   // slot (i-1)%3, data consumed
    conv(slot);
    __syncthreads();
    do_mma(slot);
  }

  const int gr = lane >> 2, gc = (lane & 3) * 2;
#pragma unroll
  for (int ms=0; ms<4; ms++)
#pragma unroll
    for (int ns=0; ns<4; ns++){
      int row = m0 + wm + ms*16 + gr;
      int col = n0 + wn + ns*8 + gc;
      if (col < Ntot){
        *reinterpret_cast<float2*>(&C[(size_t)row*Ntot + col])     = make_float2(acc[ms][ns][0], acc[ms][ns][1]);
        *reinterpret_cast<float2*>(&C[(size_t)(row+8)*Ntot + col]) = make_float2(acc[ms][ns][2], acc[ms][ns][3]);
      }
    }
}

// ---------------- small kernels ----------------
__global__ void split_k(const float* __restrict__ src, __half* __restrict__ hi,
                        __half* __restrict__ lo, int n){
  int i = blockIdx.x*256 + threadIdx.x;
  if (i < n){
    float x = src[i];
    __half h = __float2half_rn(x);
    hi[i] = h;
    lo[i] = __float2half_rn(x - __half2float(h));
  }
}

__global__ void rownorm_h(const float* __restrict__ img, const float* __restrict__ ls,
                          __half* __restrict__ outh){
  __shared__ float red[128];
  __shared__ float sc_s;
  int row = blockIdx.x, t = threadIdx.x;
  float v[4]; float s = 0.f;
#pragma unroll
  for (int j=0;j<4;j++){ v[j] = img[row*D_OUTF + t + j*128]; s += v[j]*v[j]; }
  red[t] = s; __syncthreads();
  for (int off=64; off>0; off>>=1){ if (t<off) red[t]+=red[t+off]; __syncthreads(); }
  if (t==0) sc_s = expf(*ls) / sqrtf(red[0]);
  __syncthreads();
  float sc = sc_s;
#pragma unroll
  for (int j=0;j<4;j++)
    outh[row*D_OUTF + t + j*128] = __float2half_rn(v[j]*sc);
}

// topk phase 1: 100 blocks x 256 threads over row 0 (1000 logits each)
__global__ void topk_p1(const float* __restrict__ logits){
  __shared__ float rv[256];
  __shared__ int   ri[256];
  __shared__ int   sel[TOPK];
  __shared__ float bmax_s;
  int t = threadIdx.x, b = blockIdx.x;
  int lo = b*1000, hi = lo + 1000;

  float m = -3.4e38f;
  for (int i = lo + t; i < hi; i += 256) m = fmaxf(m, logits[i]);
  rv[t] = m; __syncthreads();
  for (int s=128; s>0; s>>=1){ if (t<s) rv[t]=fmaxf(rv[t],rv[t+s]); __syncthreads(); }
  if (t==0) bmax_s = rv[0];
  __syncthreads();
  float bm = bmax_s;

  float sum = 0.f;
  for (int i = lo + t; i < hi; i += 256) sum += expf(logits[i] - bm);
  rv[t] = sum; __syncthreads();
  for (int s=128; s>0; s>>=1){ if (t<s) rv[t]+=rv[t+s]; __syncthreads(); }
  if (t==0){ g_pmax[b] = bm; g_psum[b] = rv[0]; }
  __syncthreads();

  for (int r = 0; r < TOPK; r++){
    float bv = -3.4e38f; int bi = 0x7fffffff;
    for (int i = lo + t; i < hi; i += 256){
      bool skip = false;
#pragma unroll
      for (int j = 0; j < TOPK; j++) if (j < r && sel[j] == i) skip = true;
      float v = logits[i];
      if (!skip && (v > bv || (v == bv && i < bi))){ bv = v; bi = i; }
    }
    rv[t] = bv; ri[t] = bi; __syncthreads();
    for (int s=128; s>0; s>>=1){
      if (t<s){
        if (rv[t+s] > rv[t] || (rv[t+s] == rv[t] && ri[t+s] < ri[t])){
          rv[t]=rv[t+s]; ri[t]=ri[t+s];
        }
      }
      __syncthreads();
    }
    if (t==0){ sel[r] = ri[0]; g_pidx[b*TOPK + r] = ri[0]; g_pval[b*TOPK + r] = rv[0]; }
    __syncthreads();
  }
}

// topk phase 2: merge 100 partials, write gps + probs tail
__global__ void topk_p2(const float* __restrict__ gps, float* __restrict__ out_tail){
  __shared__ float rv[512];
  __shared__ int   ri[512];
  __shared__ float gM_s, gS_s;
  int t = threadIdx.x;

  float m = (t < 100) ? g_pmax[t] : -3.4e38f;
  rv[t] = m; __syncthreads();
  for (int s=256; s>0; s>>=1){ if (t<s) rv[t]=fmaxf(rv[t],rv[t+s]); __syncthreads(); }
  if (t==0) gM_s = rv[0];
  __syncthreads();
  float M = gM_s;

  float sum = (t < 100) ? g_psum[t] * expf(g_pmax[t] - M) : 0.f;
  rv[t] = sum; __syncthreads();
  for (int s=256; s>0; s>>=1){ if (t<s) rv[t]+=rv[t+s]; __syncthreads(); }
  if (t==0) gS_s = rv[0];
  __syncthreads();
  float S = gS_s;

  float cv = (t < 100*TOPK) ? g_pval[t] : -3.4e38f;
  int   ci = (t < 100*TOPK) ? g_pidx[t] : 0x7fffffff;

  for (int r = 0; r < TOPK; r++){
    rv[t] = cv; ri[t] = ci; __syncthreads();
    for (int s=256; s>0; s>>=1){
      if (t<s){
        if (rv[t+s] > rv[t] || (rv[t+s] == rv[t] && ri[t+s] < ri[t])){
          rv[t]=rv[t+s]; ri[t]=ri[t+s];
        }
      }
      __syncthreads();
    }
    if (t == 0){
      int gi = ri[0];
      out_tail[2*r]   = gps[2*gi];
      out_tail[2*r+1] = gps[2*gi+1];
      out_tail[2*TOPK + r] = expf(rv[0] - M) / S;
    }
    __syncthreads();
    if (ci == ri[0]) cv = -3.4e38f;
    __syncthreads();
  }
}

extern "C" void kernel_launch(void* const* d_in, const int* in_sizes, int n_in,
                              void* d_out, int out_size){
  const float* img_feats   = (const float*)d_in[0];
  const float* w1          = (const float*)d_in[1];
  const float* b1          = (const float*)d_in[2];
  const float* w2          = (const float*)d_in[3];
  const float* b2          = (const float*)d_in[4];
  const float* logit_scale = (const float*)d_in[5];
  const float* loc_feats   = (const float*)d_in[6];
  const float* gps         = (const float*)d_in[7];
  float* out = (float*)d_out;

  void *ahi1,*alo1,*ahi2,*alo2,*imgb,*an;
  cudaGetSymbolAddress(&ahi1, g_Ahi1);
  cudaGetSymbolAddress(&alo1, g_Alo1);
  cudaGetSymbolAddress(&ahi2, g_Ahi2);
  cudaGetSymbolAddress(&alo2, g_Alo2);
  cudaGetSymbolAddress(&imgb, g_IMG);
  cudaGetSymbolAddress(&an,   g_AN);

  cudaFuncSetAttribute(hgemm3<true,true>,   cudaFuncAttributeMaxDynamicSharedMemorySize, 73728);
  cudaFuncSetAttribute(hgemm3<false,false>, cudaFuncAttributeMaxDynamicSharedMemorySize, 73728);
  cudaFuncSetAttribute(hgemmBig,            cudaFuncAttributeMaxDynamicSharedMemorySize, 110592);

  // 1) split input to fp16 hi/lo
  split_k<<<(N_IMG*D_INF+255)/256,256>>>(img_feats, (__half*)ahi1, (__half*)alo1, N_IMG*D_INF);
  // 2) H = relu(X W1^T + b1), epilogue writes fp16 hi/lo split directly
  hgemm3<true,true><<<dim3(4, D_HID/64), 256, 73728>>>(
      (__half*)ahi1, (__half*)alo1, w1, b1, nullptr, (__half*)ahi2, (__half*)alo2, D_HID, D_INF);
  // 3) IMG = H W2^T + b2 (f32 out)
  hgemm3<false,false><<<dim3(4, D_OUTF/64), 256, 73728>>>(
      (__half*)ahi2, (__half*)alo2, w2, b2, (float*)imgb, nullptr, nullptr, D_OUTF, D_HID);
  // 4) normalize rows, fold in exp(logit_scale) -> single fp16
  rownorm_h<<<N_IMG,128>>>((const float*)imgb, logit_scale, (__half*)an);
  // 5) logits = (s*img_n) @ loc_feats^T ; f32->f16 conversion fused via cp.async staging
  hgemmBig<<<dim3(2, (M_GAL+127)/128), 256, 110592>>>(
      (__half*)an, loc_feats, out, M_GAL, D_OUTF);
  // 6) row-0 softmax + top-5
  topk_p1<<<100,256>>>(out);
  topk_p2<<<1,512>>>(gps, out + (size_t)N_IMG*M_GAL);
}